// round 2
// baseline (speedup 1.0000x reference)
#include <cuda_runtime.h>
#include <math.h>

#define S_LEN 3072
#define D_MOD 512
#define NH 8
#define DH 64

// ---- scratch (no allocations allowed) ----
__device__ float g_Q[S_LEN * D_MOD];
__device__ float g_K[S_LEN * D_MOD];
__device__ float g_V[S_LEN * D_MOD];
__device__ float g_O[S_LEN * D_MOD];
__device__ float g_T[S_LEN * D_MOD];

// ---------------------------------------------------------------------------
// Block reductions (256 threads)
// ---------------------------------------------------------------------------
__device__ __forceinline__ float blockReduceSum256(float v, float* sh) {
    #pragma unroll
    for (int o = 16; o > 0; o >>= 1) v += __shfl_down_sync(0xffffffffu, v, o);
    int w = threadIdx.x >> 5;
    if ((threadIdx.x & 31) == 0) sh[w] = v;
    __syncthreads();
    if (threadIdx.x < 8) {
        float t = sh[threadIdx.x];
        #pragma unroll
        for (int o = 4; o > 0; o >>= 1) t += __shfl_down_sync(0xffu, t, o);
        if (threadIdx.x == 0) sh[0] = t;
    }
    __syncthreads();
    float r = sh[0];
    __syncthreads();
    return r;
}

__device__ __forceinline__ float blockReduceMax256(float v, float* sh) {
    #pragma unroll
    for (int o = 16; o > 0; o >>= 1) v = fmaxf(v, __shfl_down_sync(0xffffffffu, v, o));
    int w = threadIdx.x >> 5;
    if ((threadIdx.x & 31) == 0) sh[w] = v;
    __syncthreads();
    if (threadIdx.x < 8) {
        float t = sh[threadIdx.x];
        #pragma unroll
        for (int o = 4; o > 0; o >>= 1) t = fmaxf(t, __shfl_down_sync(0xffu, t, o));
        if (threadIdx.x == 0) sh[0] = t;
    }
    __syncthreads();
    float r = sh[0];
    __syncthreads();
    return r;
}

// ---------------------------------------------------------------------------
// Generic SGEMM + bias: C[M,N] = A[M,K] @ B[K,N] + bias   (row-major)
// BM=BN=64, BK=16, 256 threads, 4x4 per thread. M%64==0, N%64==0, K%16==0.
// ---------------------------------------------------------------------------
__global__ __launch_bounds__(256) void sgemm_bias(
    const float* __restrict__ A, const float* __restrict__ B,
    const float* __restrict__ bias, float* __restrict__ C,
    int M, int N, int K)
{
    __shared__ float As[16][64];
    __shared__ float Bs[16][64];
    int tid = threadIdx.x;
    int tx = tid & 15, ty = tid >> 4;
    int rowA = tid >> 2;          // 0..63
    int kqA  = (tid & 3) << 2;    // 0,4,8,12
    int krB  = tid >> 4;          // 0..15
    int cqB  = (tid & 15) << 2;   // 0..60
    int mbase = blockIdx.y * 64;
    int nbase = blockIdx.x * 64;

    float acc[4][4] = {};
    for (int kt = 0; kt < K; kt += 16) {
        float4 a = *(const float4*)&A[(size_t)(mbase + rowA) * K + kt + kqA];
        As[kqA + 0][rowA] = a.x; As[kqA + 1][rowA] = a.y;
        As[kqA + 2][rowA] = a.z; As[kqA + 3][rowA] = a.w;
        float4 b = *(const float4*)&B[(size_t)(kt + krB) * N + nbase + cqB];
        *(float4*)&Bs[krB][cqB] = b;
        __syncthreads();
        #pragma unroll
        for (int k = 0; k < 16; k++) {
            float av[4], bv[4];
            #pragma unroll
            for (int i = 0; i < 4; i++) av[i] = As[k][ty * 4 + i];
            #pragma unroll
            for (int j = 0; j < 4; j++) bv[j] = Bs[k][tx * 4 + j];
            #pragma unroll
            for (int i = 0; i < 4; i++)
                #pragma unroll
                for (int j = 0; j < 4; j++)
                    acc[i][j] += av[i] * bv[j];
        }
        __syncthreads();
    }
    #pragma unroll
    for (int i = 0; i < 4; i++) {
        int r = mbase + ty * 4 + i;
        float4 o;
        o.x = acc[i][0] + bias[nbase + tx * 4 + 0];
        o.y = acc[i][1] + bias[nbase + tx * 4 + 1];
        o.z = acc[i][2] + bias[nbase + tx * 4 + 2];
        o.w = acc[i][3] + bias[nbase + tx * 4 + 3];
        *(float4*)&C[(size_t)r * N + nbase + tx * 4] = o;
    }
}

// ---------------------------------------------------------------------------
// Logits: attn[h, q, k] = (1/8) * dot(Q[q, h*64:], K[k, h*64:])
// 64x64 tile per CTA, K-dim = 64 fully resident.
// ---------------------------------------------------------------------------
__global__ __launch_bounds__(256) void qk_kernel(
    const float* __restrict__ Q, const float* __restrict__ Km,
    float* __restrict__ attn)
{
    __shared__ float Qs[64][65];
    __shared__ float Ks[64][65];
    int h = blockIdx.z;
    int qbase = blockIdx.y * 64;
    int kbase = blockIdx.x * 64;
    int tid = threadIdx.x;
    int tx = tid & 15, ty = tid >> 4;

    #pragma unroll
    for (int it = 0; it < 4; it++) {
        int idx = tid + it * 256;
        int r = idx >> 4;
        int c = (idx & 15) << 2;
        float4 q4 = *(const float4*)&Q[(size_t)(qbase + r) * D_MOD + h * DH + c];
        Qs[r][c] = q4.x; Qs[r][c + 1] = q4.y; Qs[r][c + 2] = q4.z; Qs[r][c + 3] = q4.w;
        float4 k4 = *(const float4*)&Km[(size_t)(kbase + r) * D_MOD + h * DH + c];
        Ks[r][c] = k4.x; Ks[r][c + 1] = k4.y; Ks[r][c + 2] = k4.z; Ks[r][c + 3] = k4.w;
    }
    __syncthreads();

    float acc[4][4] = {};
    #pragma unroll
    for (int k = 0; k < 64; k++) {
        float av[4], bv[4];
        #pragma unroll
        for (int i = 0; i < 4; i++) av[i] = Qs[ty * 4 + i][k];
        #pragma unroll
        for (int j = 0; j < 4; j++) bv[j] = Ks[tx * 4 + j][k];
        #pragma unroll
        for (int i = 0; i < 4; i++)
            #pragma unroll
            for (int j = 0; j < 4; j++)
                acc[i][j] += av[i] * bv[j];
    }

    size_t base = (size_t)h * S_LEN * S_LEN;
    #pragma unroll
    for (int i = 0; i < 4; i++) {
        size_t roff = base + (size_t)(qbase + ty * 4 + i) * S_LEN + kbase;
        float4 o;
        o.x = acc[i][0] * 0.125f;
        o.y = acc[i][1] * 0.125f;
        o.z = acc[i][2] * 0.125f;
        o.w = acc[i][3] * 0.125f;
        *(float4*)&attn[roff + tx * 4] = o;
    }
}

// ---------------------------------------------------------------------------
// 1.5-entmax, in place over rows of length 3072.
// X = (L - max)/2; find tau by bisection on f(tau)=sum((X-tau)+^2)-1 (monotone),
// then exact quadratic solve on the identified support (matches the reference's
// sort-based tau_star exactly up to fp rounding).
// ---------------------------------------------------------------------------
__global__ __launch_bounds__(256) void entmax_kernel(float* __restrict__ attn)
{
    __shared__ float sh[8];
    float* p = attn + (size_t)blockIdx.x * S_LEN;
    int tid = threadIdx.x;

    float x[12];
    #pragma unroll
    for (int i = 0; i < 12; i++) x[i] = p[tid + (i << 8)];

    float m = x[0];
    #pragma unroll
    for (int i = 1; i < 12; i++) m = fmaxf(m, x[i]);
    m = blockReduceMax256(m, sh);

    #pragma unroll
    for (int i = 0; i < 12; i++) x[i] = (x[i] - m) * 0.5f;

    // root is in [-1, 0]: f(-1) >= 1 (max element contributes 1), f(0) = 0
    float lo = -1.0f, hi = 0.0f;
    for (int it = 0; it < 30; it++) {
        float mid = 0.5f * (lo + hi);
        float s = 0.0f;
        #pragma unroll
        for (int i = 0; i < 12; i++) {
            float d = fmaxf(x[i] - mid, 0.0f);
            s += d * d;
        }
        s = blockReduceSum256(s, sh);
        if (s > 1.0f) lo = mid; else hi = mid;
    }
    float tau_b = 0.5f * (lo + hi);

    // exact solve on support {x > tau_b}
    float s1 = 0.0f, s2 = 0.0f, cn = 0.0f;
    #pragma unroll
    for (int i = 0; i < 12; i++) {
        if (x[i] > tau_b) { s1 += x[i]; s2 += x[i] * x[i]; cn += 1.0f; }
    }
    s1 = blockReduceSum256(s1, sh);
    s2 = blockReduceSum256(s2, sh);
    cn = blockReduceSum256(cn, sh);
    float n = fmaxf(cn, 1.0f);
    float disc = fmaxf(s1 * s1 - n * (s2 - 1.0f), 0.0f);
    float tstar = (s1 - sqrtf(disc)) / n;

    #pragma unroll
    for (int i = 0; i < 12; i++) {
        float d = fmaxf(x[i] - tstar, 0.0f);
        p[tid + (i << 8)] = d * d;
    }
}

// ---------------------------------------------------------------------------
// O[q, h*64+d] = sum_k attn[h,q,k] * V[k, h*64+d]
// BM=64, BN=64 (full head dim), BK=64.
// ---------------------------------------------------------------------------
__global__ __launch_bounds__(256) void av_kernel(
    const float* __restrict__ attn, const float* __restrict__ V,
    float* __restrict__ O)
{
    __shared__ float As[64][65];
    __shared__ float Bs[64][64];
    int h = blockIdx.z;
    int qbase = blockIdx.y * 64;
    int tid = threadIdx.x;
    int tx = tid & 15, ty = tid >> 4;
    const float* ap = attn + (size_t)h * S_LEN * S_LEN;

    float acc[4][4] = {};
    for (int kt = 0; kt < S_LEN; kt += 64) {
        #pragma unroll
        for (int it = 0; it < 4; it++) {
            int idx = tid + it * 256;
            int r  = idx >> 4;          // 0..63
            int kq = (idx & 15) << 2;   // 0..60
            float4 a4 = *(const float4*)&ap[(size_t)(qbase + r) * S_LEN + kt + kq];
            As[r][kq] = a4.x; As[r][kq + 1] = a4.y; As[r][kq + 2] = a4.z; As[r][kq + 3] = a4.w;
            float4 b4 = *(const float4*)&V[(size_t)(kt + r) * D_MOD + h * DH + kq];
            *(float4*)&Bs[r][kq] = b4;
        }
        __syncthreads();
        #pragma unroll
        for (int k = 0; k < 64; k++) {
            float av[4], bv[4];
            #pragma unroll
            for (int i = 0; i < 4; i++) av[i] = As[ty * 4 + i][k];
            #pragma unroll
            for (int j = 0; j < 4; j++) bv[j] = Bs[k][tx * 4 + j];
            #pragma unroll
            for (int i = 0; i < 4; i++)
                #pragma unroll
                for (int j = 0; j < 4; j++)
                    acc[i][j] += av[i] * bv[j];
        }
        __syncthreads();
    }
    #pragma unroll
    for (int i = 0; i < 4; i++) {
        size_t roff = (size_t)(qbase + ty * 4 + i) * D_MOD + h * DH;
        float4 o;
        o.x = acc[i][0]; o.y = acc[i][1]; o.z = acc[i][2]; o.w = acc[i][3];
        *(float4*)&O[roff + tx * 4] = o;
    }
}

// ---------------------------------------------------------------------------
// LayerNorm(residual + proj): out = LN(t + x) * gamma + beta
// one CTA per row of 512, 256 threads x 2 elements
// ---------------------------------------------------------------------------
__global__ __launch_bounds__(256) void ln_kernel(
    const float* __restrict__ t, const float* __restrict__ x,
    const float* __restrict__ gamma, const float* __restrict__ beta,
    float* __restrict__ out)
{
    __shared__ float sh[8];
    size_t base = (size_t)blockIdx.x * D_MOD;
    int tid = threadIdx.x;
    float v0 = t[base + tid]       + x[base + tid];
    float v1 = t[base + tid + 256] + x[base + tid + 256];
    float s = blockReduceSum256(v0 + v1, sh);
    float mu = s * (1.0f / 512.0f);
    float d0 = v0 - mu, d1 = v1 - mu;
    float vs = blockReduceSum256(d0 * d0 + d1 * d1, sh);
    float inv = rsqrtf(vs * (1.0f / 512.0f) + 1e-6f);
    out[base + tid]       = d0 * inv * gamma[tid]       + beta[tid];
    out[base + tid + 256] = d1 * inv * gamma[tid + 256] + beta[tid + 256];
}

// ---------------------------------------------------------------------------
extern "C" void kernel_launch(void* const* d_in, const int* in_sizes, int n_in,
                              void* d_out, int out_size)
{
    const float* x     = (const float*)d_in[0];
    const float* Wq    = (const float*)d_in[1];
    const float* bq    = (const float*)d_in[2];
    const float* Wk    = (const float*)d_in[3];
    const float* bk    = (const float*)d_in[4];
    const float* Wv    = (const float*)d_in[5];
    const float* bv    = (const float*)d_in[6];
    const float* Wo    = (const float*)d_in[7];
    const float* bo    = (const float*)d_in[8];
    const float* gamma = (const float*)d_in[9];
    const float* beta  = (const float*)d_in[10];

    float* out  = (float*)d_out;
    float* attn = out + (size_t)S_LEN * D_MOD;

    float *Qp, *Kp, *Vp, *Op, *Tp;
    cudaGetSymbolAddress((void**)&Qp, g_Q);
    cudaGetSymbolAddress((void**)&Kp, g_K);
    cudaGetSymbolAddress((void**)&Vp, g_V);
    cudaGetSymbolAddress((void**)&Op, g_O);
    cudaGetSymbolAddress((void**)&Tp, g_T);

    dim3 gProj(D_MOD / 64, S_LEN / 64);           // (8, 48)
    sgemm_bias<<<gProj, 256>>>(x, Wq, bq, Qp, S_LEN, D_MOD, D_MOD);
    sgemm_bias<<<gProj, 256>>>(x, Wk, bk, Kp, S_LEN, D_MOD, D_MOD);
    sgemm_bias<<<gProj, 256>>>(x, Wv, bv, Vp, S_LEN, D_MOD, D_MOD);

    qk_kernel<<<dim3(S_LEN / 64, S_LEN / 64, NH), 256>>>(Qp, Kp, attn);

    entmax_kernel<<<NH * S_LEN, 256>>>(attn);

    av_kernel<<<dim3(1, S_LEN / 64, NH), 256>>>(attn, Vp, Op);

    sgemm_bias<<<gProj, 256>>>(Op, Wo, bo, Tp, S_LEN, D_MOD, D_MOD);

    ln_kernel<<<S_LEN, 256>>>(Tp, x, gamma, beta, out);
}

// round 4
// speedup vs baseline: 1.8780x; 1.8780x over previous
#include <cuda_runtime.h>
#include <math.h>

#define S_LEN 3072
#define D_MOD 512
#define NH 8
#define DH 64

// ---- scratch (no allocations allowed) ----
__device__ float g_Q[S_LEN * D_MOD];
__device__ float g_K[S_LEN * D_MOD];
__device__ float g_V[S_LEN * D_MOD];
__device__ float g_O[S_LEN * D_MOD];
__device__ float g_T[S_LEN * D_MOD];

struct QKVArgs {
    const float* W[3];
    const float* b[3];
    float* C[3];
};

// ---------------------------------------------------------------------------
// tf32 helpers
// ---------------------------------------------------------------------------
__device__ __forceinline__ unsigned f2tf(float f) {
    unsigned u;
    asm("cvt.rna.tf32.f32 %0, %1;" : "=r"(u) : "f"(f));
    return u;
}

__device__ __forceinline__ void mma8(float* c,
    unsigned a0, unsigned a1, unsigned a2, unsigned a3,
    unsigned b0, unsigned b1)
{
    asm volatile(
        "mma.sync.aligned.m16n8k8.row.col.f32.tf32.tf32.f32 "
        "{%0,%1,%2,%3}, {%4,%5,%6,%7}, {%8,%9}, {%0,%1,%2,%3};"
        : "+f"(c[0]), "+f"(c[1]), "+f"(c[2]), "+f"(c[3])
        : "r"(a0), "r"(a1), "r"(a2), "r"(a3), "r"(b0), "r"(b1));
}

// ---------------------------------------------------------------------------
// Block reductions (256 threads)
// ---------------------------------------------------------------------------
__device__ __forceinline__ float blockReduceMax256(float v, float* sh) {
    #pragma unroll
    for (int o = 16; o > 0; o >>= 1) v = fmaxf(v, __shfl_down_sync(0xffffffffu, v, o));
    int w = threadIdx.x >> 5;
    if ((threadIdx.x & 31) == 0) sh[w] = v;
    __syncthreads();
    if (threadIdx.x < 8) {
        float t = sh[threadIdx.x];
        #pragma unroll
        for (int o = 4; o > 0; o >>= 1) t = fmaxf(t, __shfl_down_sync(0xffu, t, o));
        if (threadIdx.x == 0) sh[0] = t;
    }
    __syncthreads();
    float r = sh[0];
    __syncthreads();
    return r;
}

__device__ __forceinline__ float blockReduceSum256(float v, float* sh) {
    #pragma unroll
    for (int o = 16; o > 0; o >>= 1) v += __shfl_down_sync(0xffffffffu, v, o);
    int w = threadIdx.x >> 5;
    if ((threadIdx.x & 31) == 0) sh[w] = v;
    __syncthreads();
    if (threadIdx.x < 8) {
        float t = sh[threadIdx.x];
        #pragma unroll
        for (int o = 4; o > 0; o >>= 1) t += __shfl_down_sync(0xffu, t, o);
        if (threadIdx.x == 0) sh[0] = t;
    }
    __syncthreads();
    float r = sh[0];
    __syncthreads();
    return r;
}

// reduce 3 sums at once; sh must have >= 24 floats
__device__ __forceinline__ float3 blockReduceSum3(float a, float b, float c, float* sh) {
    #pragma unroll
    for (int o = 16; o > 0; o >>= 1) {
        a += __shfl_down_sync(0xffffffffu, a, o);
        b += __shfl_down_sync(0xffffffffu, b, o);
        c += __shfl_down_sync(0xffffffffu, c, o);
    }
    int w = threadIdx.x >> 5;
    if ((threadIdx.x & 31) == 0) { sh[w] = a; sh[w + 8] = b; sh[w + 16] = c; }
    __syncthreads();
    if (threadIdx.x < 8) {
        a = sh[threadIdx.x]; b = sh[threadIdx.x + 8]; c = sh[threadIdx.x + 16];
        #pragma unroll
        for (int o = 4; o > 0; o >>= 1) {
            a += __shfl_down_sync(0xffu, a, o);
            b += __shfl_down_sync(0xffu, b, o);
            c += __shfl_down_sync(0xffu, c, o);
        }
        if (threadIdx.x == 0) { sh[0] = a; sh[8] = b; sh[16] = c; }
    }
    __syncthreads();
    float3 r = make_float3(sh[0], sh[8], sh[16]);
    __syncthreads();
    return r;
}

// ---------------------------------------------------------------------------
// Core tf32 GEMM tile body: CTA 64x64, BK=64, 8 warps (2m x 4n), warp 32x16.
// ---------------------------------------------------------------------------
__device__ __forceinline__ void gemm_body(
    const float* __restrict__ A, const float* __restrict__ W,
    float c[2][2][4], unsigned (*Xs)[68], unsigned (*Ws)[72],
    int mbase, int nbase, int N, int K)
{
    int tid = threadIdx.x;
    int lane = tid & 31, wid = tid >> 5;
    int gid = lane >> 2, tig = lane & 3;
    int wm = wid & 1, wn = wid >> 1;

    for (int kt = 0; kt < K; kt += 64) {
        #pragma unroll
        for (int i = 0; i < 4; i++) {
            int idx = tid + i * 256;          // 0..1023
            int r = idx >> 4;                 // 0..63
            int cc = (idx & 15) << 2;         // 0..60
            float4 a4 = *(const float4*)&A[(size_t)(mbase + r) * K + kt + cc];
            uint4 ua; ua.x = f2tf(a4.x); ua.y = f2tf(a4.y); ua.z = f2tf(a4.z); ua.w = f2tf(a4.w);
            *(uint4*)&Xs[r][cc] = ua;
            float4 b4 = *(const float4*)&W[(size_t)(kt + r) * N + nbase + cc];
            uint4 ub; ub.x = f2tf(b4.x); ub.y = f2tf(b4.y); ub.z = f2tf(b4.z); ub.w = f2tf(b4.w);
            *(uint4*)&Ws[r][cc] = ub;
        }
        __syncthreads();
        #pragma unroll
        for (int ks = 0; ks < 8; ks++) {
            int kb = ks * 8;
            unsigned a[2][4], b[2][2];
            #pragma unroll
            for (int mt = 0; mt < 2; mt++) {
                int rb = wm * 32 + mt * 16 + gid;
                a[mt][0] = Xs[rb][kb + tig];
                a[mt][1] = Xs[rb + 8][kb + tig];
                a[mt][2] = Xs[rb][kb + tig + 4];
                a[mt][3] = Xs[rb + 8][kb + tig + 4];
            }
            #pragma unroll
            for (int nt = 0; nt < 2; nt++) {
                int cb = wn * 16 + nt * 8 + gid;
                b[nt][0] = Ws[kb + tig][cb];
                b[nt][1] = Ws[kb + tig + 4][cb];
            }
            #pragma unroll
            for (int mt = 0; mt < 2; mt++)
                #pragma unroll
                for (int nt = 0; nt < 2; nt++)
                    mma8(c[mt][nt], a[mt][0], a[mt][1], a[mt][2], a[mt][3], b[nt][0], b[nt][1]);
        }
        __syncthreads();
    }
}

// ---------------------------------------------------------------------------
// Fused QKV projection: z-slice selects (W, b, C). A is x for all three.
// ---------------------------------------------------------------------------
__global__ __launch_bounds__(256) void qkv_tc(const float* __restrict__ A, QKVArgs args)
{
    __shared__ unsigned Xs[64][68];
    __shared__ unsigned Ws[64][72];
    int z = blockIdx.z;
    const float* W = args.W[z];
    const float* bias = args.b[z];
    float* C = args.C[z];
    int mbase = blockIdx.y * 64;
    int nbase = blockIdx.x * 64;

    float c[2][2][4] = {};
    gemm_body(A, W, c, Xs, Ws, mbase, nbase, D_MOD, D_MOD);

    int tid = threadIdx.x;
    int lane = tid & 31, wid = tid >> 5;
    int gid = lane >> 2, tig = lane & 3;
    int wm = wid & 1, wn = wid >> 1;
    #pragma unroll
    for (int mt = 0; mt < 2; mt++) {
        int r0 = mbase + wm * 32 + mt * 16 + gid;
        #pragma unroll
        for (int nt = 0; nt < 2; nt++) {
            int col = nbase + wn * 16 + nt * 8 + 2 * tig;
            float bx = bias[col], by = bias[col + 1];
            float2 o0; o0.x = c[mt][nt][0] + bx; o0.y = c[mt][nt][1] + by;
            *(float2*)&C[(size_t)r0 * D_MOD + col] = o0;
            float2 o1; o1.x = c[mt][nt][2] + bx; o1.y = c[mt][nt][3] + by;
            *(float2*)&C[(size_t)(r0 + 8) * D_MOD + col] = o1;
        }
    }
}

// ---------------------------------------------------------------------------
// Output projection: C = A @ W + bias
// ---------------------------------------------------------------------------
__global__ __launch_bounds__(256) void proj_tc(
    const float* __restrict__ A, const float* __restrict__ W,
    const float* __restrict__ bias, float* __restrict__ C)
{
    __shared__ unsigned Xs[64][68];
    __shared__ unsigned Ws[64][72];
    int mbase = blockIdx.y * 64;
    int nbase = blockIdx.x * 64;

    float c[2][2][4] = {};
    gemm_body(A, W, c, Xs, Ws, mbase, nbase, D_MOD, D_MOD);

    int tid = threadIdx.x;
    int lane = tid & 31, wid = tid >> 5;
    int gid = lane >> 2, tig = lane & 3;
    int wm = wid & 1, wn = wid >> 1;
    #pragma unroll
    for (int mt = 0; mt < 2; mt++) {
        int r0 = mbase + wm * 32 + mt * 16 + gid;
        #pragma unroll
        for (int nt = 0; nt < 2; nt++) {
            int col = nbase + wn * 16 + nt * 8 + 2 * tig;
            float bx = bias[col], by = bias[col + 1];
            float2 o0; o0.x = c[mt][nt][0] + bx; o0.y = c[mt][nt][1] + by;
            *(float2*)&C[(size_t)r0 * D_MOD + col] = o0;
            float2 o1; o1.x = c[mt][nt][2] + bx; o1.y = c[mt][nt][3] + by;
            *(float2*)&C[(size_t)(r0 + 8) * D_MOD + col] = o1;
        }
    }
}

// ---------------------------------------------------------------------------
// Logits (tf32): attn[h,q,k] = (1/8) * dot(Q[q, h*64:], K[k, h*64:])
// CTA 64(q) x 64(k), K-dim 64 resident.
// ---------------------------------------------------------------------------
__global__ __launch_bounds__(256) void qk_tc(
    const float* __restrict__ Q, const float* __restrict__ Km,
    float* __restrict__ attn)
{
    __shared__ unsigned Qs[64][68];
    __shared__ unsigned Ks[64][68];
    int h = blockIdx.z;
    int qbase = blockIdx.y * 64;
    int kbase = blockIdx.x * 64;
    int tid = threadIdx.x;
    int lane = tid & 31, wid = tid >> 5;
    int gid = lane >> 2, tig = lane & 3;
    int wm = wid & 1, wn = wid >> 1;

    #pragma unroll
    for (int i = 0; i < 4; i++) {
        int idx = tid + i * 256;
        int r = idx >> 4;
        int cc = (idx & 15) << 2;
        float4 q4 = *(const float4*)&Q[(size_t)(qbase + r) * D_MOD + h * DH + cc];
        uint4 uq; uq.x = f2tf(q4.x); uq.y = f2tf(q4.y); uq.z = f2tf(q4.z); uq.w = f2tf(q4.w);
        *(uint4*)&Qs[r][cc] = uq;
        float4 k4 = *(const float4*)&Km[(size_t)(kbase + r) * D_MOD + h * DH + cc];
        uint4 uk; uk.x = f2tf(k4.x); uk.y = f2tf(k4.y); uk.z = f2tf(k4.z); uk.w = f2tf(k4.w);
        *(uint4*)&Ks[r][cc] = uk;
    }
    __syncthreads();

    float c[2][2][4] = {};
    #pragma unroll
    for (int ks = 0; ks < 8; ks++) {
        int kb = ks * 8;
        unsigned a[2][4], b[2][2];
        #pragma unroll
        for (int mt = 0; mt < 2; mt++) {
            int rb = wm * 32 + mt * 16 + gid;
            a[mt][0] = Qs[rb][kb + tig];
            a[mt][1] = Qs[rb + 8][kb + tig];
            a[mt][2] = Qs[rb][kb + tig + 4];
            a[mt][3] = Qs[rb + 8][kb + tig + 4];
        }
        #pragma unroll
        for (int nt = 0; nt < 2; nt++) {
            int cb = wn * 16 + nt * 8 + gid;
            b[nt][0] = Ks[cb][kb + tig];
            b[nt][1] = Ks[cb][kb + tig + 4];
        }
        #pragma unroll
        for (int mt = 0; mt < 2; mt++)
            #pragma unroll
            for (int nt = 0; nt < 2; nt++)
                mma8(c[mt][nt], a[mt][0], a[mt][1], a[mt][2], a[mt][3], b[nt][0], b[nt][1]);
    }

    size_t base = (size_t)h * S_LEN * S_LEN;
    #pragma unroll
    for (int mt = 0; mt < 2; mt++) {
        int r0 = qbase + wm * 32 + mt * 16 + gid;
        #pragma unroll
        for (int nt = 0; nt < 2; nt++) {
            int col = kbase + wn * 16 + nt * 8 + 2 * tig;
            float2 o0; o0.x = c[mt][nt][0] * 0.125f; o0.y = c[mt][nt][1] * 0.125f;
            *(float2*)&attn[base + (size_t)r0 * S_LEN + col] = o0;
            float2 o1; o1.x = c[mt][nt][2] * 0.125f; o1.y = c[mt][nt][3] * 0.125f;
            *(float2*)&attn[base + (size_t)(r0 + 8) * S_LEN + col] = o1;
        }
    }
}

// ---------------------------------------------------------------------------
// 1.5-entmax, in place over rows of length 3072.
// X=(L-max)/2; 9 rounds of 3-point bisection (2 bits/round -> 18 bits on tau),
// then exact quadratic solve on the identified support.
// ---------------------------------------------------------------------------
__global__ __launch_bounds__(256) void entmax_kernel(float* __restrict__ attn)
{
    __shared__ float sh[24];
    float* p = attn + (size_t)blockIdx.x * S_LEN;
    int tid = threadIdx.x;

    float x[12];
    #pragma unroll
    for (int i = 0; i < 12; i++) x[i] = p[tid + (i << 8)];

    float m = x[0];
    #pragma unroll
    for (int i = 1; i < 12; i++) m = fmaxf(m, x[i]);
    m = blockReduceMax256(m, sh);

    #pragma unroll
    for (int i = 0; i < 12; i++) x[i] = (x[i] - m) * 0.5f;

    // root of f(tau)=sum((x-tau)+^2)-1 lies in [-1, 0]
    float lo = -1.0f, hi = 0.0f;
    for (int it = 0; it < 9; it++) {
        float w = (hi - lo) * 0.25f;
        float m1 = lo + w, m2 = lo + 2.0f * w, m3 = hi - w;
        float s1 = 0.0f, s2 = 0.0f, s3 = 0.0f;
        #pragma unroll
        for (int i = 0; i < 12; i++) {
            float d1 = fmaxf(x[i] - m1, 0.0f); s1 += d1 * d1;
            float d2 = fmaxf(x[i] - m2, 0.0f); s2 += d2 * d2;
            float d3 = fmaxf(x[i] - m3, 0.0f); s3 += d3 * d3;
        }
        float3 r = blockReduceSum3(s1, s2, s3, sh);
        if (r.z > 1.0f)      { lo = m3; }
        else if (r.y > 1.0f) { lo = m2; hi = m3; }
        else if (r.x > 1.0f) { lo = m1; hi = m2; }
        else                 { hi = m1; }
    }
    float tau_b = 0.5f * (lo + hi);

    // exact solve on support {x > tau_b}
    float s1 = 0.0f, s2 = 0.0f, cn = 0.0f;
    #pragma unroll
    for (int i = 0; i < 12; i++) {
        if (x[i] > tau_b) { s1 += x[i]; s2 += x[i] * x[i]; cn += 1.0f; }
    }
    float3 r = blockReduceSum3(s1, s2, cn, sh);
    float n = fmaxf(r.z, 1.0f);
    float disc = fmaxf(r.x * r.x - n * (r.y - 1.0f), 0.0f);
    float tstar = (r.x - sqrtf(disc)) / n;

    #pragma unroll
    for (int i = 0; i < 12; i++) {
        float d = fmaxf(x[i] - tstar, 0.0f);
        p[tid + (i << 8)] = d * d;
    }
}

// ---------------------------------------------------------------------------
// AV (tf32): O[q, h*64+d] = sum_k attn[h,q,k] * V[k, h*64+d]
// CTA 64(q) x 64(d), BK=64 over S.
// ---------------------------------------------------------------------------
__global__ __launch_bounds__(256) void av_tc(
    const float* __restrict__ attn, const float* __restrict__ V,
    float* __restrict__ O)
{
    __shared__ unsigned As[64][68];
    __shared__ unsigned Vs[64][72];
    int h = blockIdx.y;
    int mbase = blockIdx.x * 64;
    int tid = threadIdx.x;
    int lane = tid & 31, wid = tid >> 5;
    int gid = lane >> 2, tig = lane & 3;
    int wm = wid & 1, wn = wid >> 1;
    const float* ap = attn + (size_t)h * S_LEN * S_LEN;

    float c[2][2][4] = {};
    for (int kt = 0; kt < S_LEN; kt += 64) {
        #pragma unroll
        for (int i = 0; i < 4; i++) {
            int idx = tid + i * 256;
            int r = idx >> 4;
            int cc = (idx & 15) << 2;
            float4 a4 = *(const float4*)&ap[(size_t)(mbase + r) * S_LEN + kt + cc];
            uint4 ua; ua.x = f2tf(a4.x); ua.y = f2tf(a4.y); ua.z = f2tf(a4.z); ua.w = f2tf(a4.w);
            *(uint4*)&As[r][cc] = ua;
            float4 b4 = *(const float4*)&V[(size_t)(kt + r) * D_MOD + h * DH + cc];
            uint4 ub; ub.x = f2tf(b4.x); ub.y = f2tf(b4.y); ub.z = f2tf(b4.z); ub.w = f2tf(b4.w);
            *(uint4*)&Vs[r][cc] = ub;
        }
        __syncthreads();
        #pragma unroll
        for (int ks = 0; ks < 8; ks++) {
            int kb = ks * 8;
            unsigned a[2][4], b[2][2];
            #pragma unroll
            for (int mt = 0; mt < 2; mt++) {
                int rb = wm * 32 + mt * 16 + gid;
                a[mt][0] = As[rb][kb + tig];
                a[mt][1] = As[rb + 8][kb + tig];
                a[mt][2] = As[rb][kb + tig + 4];
                a[mt][3] = As[rb + 8][kb + tig + 4];
            }
            #pragma unroll
            for (int nt = 0; nt < 2; nt++) {
                int cb = wn * 16 + nt * 8 + gid;
                b[nt][0] = Vs[kb + tig][cb];
                b[nt][1] = Vs[kb + tig + 4][cb];
            }
            #pragma unroll
            for (int mt = 0; mt < 2; mt++)
                #pragma unroll
                for (int nt = 0; nt < 2; nt++)
                    mma8(c[mt][nt], a[mt][0], a[mt][1], a[mt][2], a[mt][3], b[nt][0], b[nt][1]);
        }
        __syncthreads();
    }
    #pragma unroll
    for (int mt = 0; mt < 2; mt++) {
        int r0 = mbase + wm * 32 + mt * 16 + gid;
        #pragma unroll
        for (int nt = 0; nt < 2; nt++) {
            int col = h * DH + wn * 16 + nt * 8 + 2 * tig;
            float2 o0; o0.x = c[mt][nt][0]; o0.y = c[mt][nt][1];
            *(float2*)&O[(size_t)r0 * D_MOD + col] = o0;
            float2 o1; o1.x = c[mt][nt][2]; o1.y = c[mt][nt][3];
            *(float2*)&O[(size_t)(r0 + 8) * D_MOD + col] = o1;
        }
    }
}

// ---------------------------------------------------------------------------
// LayerNorm(residual + proj): out = LN(t + x) * gamma + beta
// ---------------------------------------------------------------------------
__global__ __launch_bounds__(256) void ln_kernel(
    const float* __restrict__ t, const float* __restrict__ x,
    const float* __restrict__ gamma, const float* __restrict__ beta,
    float* __restrict__ out)
{
    __shared__ float sh[8];
    size_t base = (size_t)blockIdx.x * D_MOD;
    int tid = threadIdx.x;
    float v0 = t[base + tid]       + x[base + tid];
    float v1 = t[base + tid + 256] + x[base + tid + 256];
    float s = blockReduceSum256(v0 + v1, sh);
    float mu = s * (1.0f / 512.0f);
    float d0 = v0 - mu, d1 = v1 - mu;
    float vs = blockReduceSum256(d0 * d0 + d1 * d1, sh);
    float inv = rsqrtf(vs * (1.0f / 512.0f) + 1e-6f);
    out[base + tid]       = d0 * inv * gamma[tid]       + beta[tid];
    out[base + tid + 256] = d1 * inv * gamma[tid + 256] + beta[tid + 256];
}

// ---------------------------------------------------------------------------
extern "C" void kernel_launch(void* const* d_in, const int* in_sizes, int n_in,
                              void* d_out, int out_size)
{
    const float* x     = (const float*)d_in[0];
    const float* Wq    = (const float*)d_in[1];
    const float* bq    = (const float*)d_in[2];
    const float* Wk    = (const float*)d_in[3];
    const float* bk    = (const float*)d_in[4];
    const float* Wv    = (const float*)d_in[5];
    const float* bv    = (const float*)d_in[6];
    const float* Wo    = (const float*)d_in[7];
    const float* bo    = (const float*)d_in[8];
    const float* gamma = (const float*)d_in[9];
    const float* beta  = (const float*)d_in[10];

    float* out  = (float*)d_out;
    float* attn = out + (size_t)S_LEN * D_MOD;

    float *Qp, *Kp, *Vp, *Op, *Tp;
    cudaGetSymbolAddress((void**)&Qp, g_Q);
    cudaGetSymbolAddress((void**)&Kp, g_K);
    cudaGetSymbolAddress((void**)&Vp, g_V);
    cudaGetSymbolAddress((void**)&Op, g_O);
    cudaGetSymbolAddress((void**)&Tp, g_T);

    QKVArgs qa;
    qa.W[0] = Wq; qa.W[1] = Wk; qa.W[2] = Wv;
    qa.b[0] = bq; qa.b[1] = bk; qa.b[2] = bv;
    qa.C[0] = Qp; qa.C[1] = Kp; qa.C[2] = Vp;

    qkv_tc<<<dim3(D_MOD / 64, S_LEN / 64, 3), 256>>>(x, qa);

    qk_tc<<<dim3(S_LEN / 64, S_LEN / 64, NH), 256>>>(Qp, Kp, attn);

    entmax_kernel<<<NH * S_LEN, 256>>>(attn);

    av_tc<<<dim3(S_LEN / 64, NH), 256>>>(attn, Vp, Op);

    proj_tc<<<dim3(D_MOD / 64, S_LEN / 64), 256>>>(Op, Wo, bo, Tp);

    ln_kernel<<<S_LEN, 256>>>(Tp, x, gamma, beta, out);
}